// round 14
// baseline (speedup 1.0000x reference)
#include <cuda_runtime.h>

#define NB_VARS 2000000
#define M0 4000000
#define M1 1000000
#define M2 500000
#define M3 125000
#define E1 8000000
#define E3 1000000

#define SSEG 2048   // smem accumulator slots per block (block covers 1024 sorted edges)

// Scratch (allocation-free rule: __device__ globals)
__device__ float g_y0[M0];
__device__ float g_y1[M1];
__device__ float g_y2[M2];

// Fused input encoding: x = [0, 1, p0, 1-p0, p1, 1-p1, ...]
__device__ __forceinline__ float leaf_val(const float* __restrict__ xp, int idx) {
    if (idx >= 2) {
        float p = __ldg(xp + ((idx - 2) >> 1));
        return (idx & 1) ? (1.0f - p) : p;
    }
    return (float)idx;  // 0 -> 0.0, 1 -> 1.0
}

// Layer 0: 2 products per thread (4 gathers), float2 store. 2M threads.
// Also zeroes g_y1 and d_out (PDL chain guarantees completion before consumers).
__global__ void __launch_bounds__(256) layer0_kernel(const float* __restrict__ xp,
                                                     const int4* __restrict__ ix,
                                                     float* __restrict__ out_zero) {
    int t = blockIdx.x * blockDim.x + threadIdx.x;     // [0, M0/2)
    if (t < M1 / 4) ((float4*)g_y1)[t] = make_float4(0.f, 0.f, 0.f, 0.f);
    if (t < M3 / 4) ((float4*)out_zero)[t] = make_float4(0.f, 0.f, 0.f, 0.f);
    if (t >= M0 / 2) return;
    int4 v = __ldg(ix + t);
    float2 r;
    r.x = leaf_val(xp, v.x) * leaf_val(xp, v.y);
    r.y = leaf_val(xp, v.z) * leaf_val(xp, v.w);
    ((float2*)g_y0)[t] = r;
}

// Sorted segment-sum, 4 edges/thread, smem-staged:
//  - local run-merge (as before)
//  - run flushes go to a block-local smem accumulator indexed by (seg - segFirst)
//    (sorted ix_out => block's segment range is ~#runs wide; SSEG covers gaps)
//  - cooperative flush: one global atomic per nonzero slot (zero-skip safe: dst pre-zeroed)
//  - out-of-range ids fall back to direct global atomics (correct unconditionally)
// PDL: index streams + smem init happen before the grid dependency sync.
__device__ __forceinline__ void segsum_smem(const int4* __restrict__ ix_in,
                                            const int4* __restrict__ ix_out,
                                            const int* __restrict__ ixo_scalar,
                                            const float* __restrict__ src,
                                            float* __restrict__ dst,
                                            int nthreads, bool trigger) {
    __shared__ float acc[SSEG];
    __shared__ int sFirstSh;
    int tid = threadIdx.x;
    int t = blockIdx.x * blockDim.x + tid;
    bool valid = (t < nthreads);

    if (tid == 0) sFirstSh = __ldg(ixo_scalar + (long long)blockIdx.x * blockDim.x * 4);
    #pragma unroll
    for (int i = tid; i < SSEG; i += 256) acc[i] = 0.f;

    int4 s, g;
    if (valid) {
        s = __ldg(ix_out + t);
        g = __ldg(ix_in + t);
    }
    cudaGridDependencySynchronize();
    if (trigger) cudaTriggerProgrammaticLaunchCompletion();
    __syncthreads();
    int sFirst = sFirstSh;

    if (valid) {
        float v0 = __ldg(src + g.x);
        float v1 = __ldg(src + g.y);
        float v2 = __ldg(src + g.z);
        float v3 = __ldg(src + g.w);
        float accv = v0;
        int cur = s.x;
        #define FLUSH(seg, val) do {                                   \
            int rel = (seg) - sFirst;                                  \
            if ((unsigned)rel < SSEG) atomicAdd(&acc[rel], (val));     \
            else atomicAdd(dst + (seg), (val));                        \
        } while (0)
        if (s.y == cur) accv += v1; else { FLUSH(cur, accv); cur = s.y; accv = v1; }
        if (s.z == cur) accv += v2; else { FLUSH(cur, accv); cur = s.z; accv = v2; }
        if (s.w == cur) accv += v3; else { FLUSH(cur, accv); cur = s.w; accv = v3; }
        FLUSH(cur, accv);
        #undef FLUSH
    }
    __syncthreads();
    #pragma unroll
    for (int i = tid; i < SSEG; i += 256) {
        float a = acc[i];
        if (a != 0.f) atomicAdd(dst + sFirst + i, a);
    }
}

__global__ void __launch_bounds__(256) segsum1_kernel(const int4* __restrict__ ix_in,
                                                      const int4* __restrict__ ix_out,
                                                      const int* __restrict__ ixo_s) {
    segsum_smem(ix_in, ix_out, ixo_s, g_y0, g_y1, E1 / 4, true);
}

__global__ void __launch_bounds__(256) segsum3_kernel(const int4* __restrict__ ix_in,
                                                      const int4* __restrict__ ix_out,
                                                      const int* __restrict__ ixo_s,
                                                      float* __restrict__ out) {
    segsum_smem(ix_in, ix_out, ixo_s, g_y2, out, E3 / 4, false);
}

// Layer 2: 2 products per thread over g_y1 -> g_y2. 250K threads. PDL.
__global__ void __launch_bounds__(256) layer2_kernel(const int4* __restrict__ ix) {
    int t = blockIdx.x * blockDim.x + threadIdx.x;     // [0, M2/2)
    if (t >= M2 / 2) {
        cudaGridDependencySynchronize();
        return;
    }
    int4 v = __ldg(ix + t);
    cudaGridDependencySynchronize();        // wait for segsum1 (g_y1 final)
    cudaTriggerProgrammaticLaunchCompletion();
    float2 r;
    r.x = __ldg(g_y1 + v.x) * __ldg(g_y1 + v.y);
    r.y = __ldg(g_y1 + v.z) * __ldg(g_y1 + v.w);
    ((float2*)g_y2)[t] = r;
}

template <typename... Args>
static void launch_pdl(void (*kern)(Args...), int grid, int block, Args... args) {
    cudaLaunchConfig_t cfg = {};
    cfg.gridDim = dim3(grid, 1, 1);
    cfg.blockDim = dim3(block, 1, 1);
    cudaLaunchAttribute attr[1];
    attr[0].id = cudaLaunchAttributeProgrammaticStreamSerialization;
    attr[0].val.programmaticStreamSerializationAllowed = 1;
    cfg.attrs = attr;
    cfg.numAttrs = 1;
    cfg.stream = 0;
    cudaLaunchKernelEx(&cfg, kern, args...);
}

extern "C" void kernel_launch(void* const* d_in, const int* in_sizes, int n_in,
                              void* d_out, int out_size) {
    const float* x_pos   = (const float*)d_in[0];
    const int*   ix_in0  = (const int*)d_in[1];
    const int*   ix_in1  = (const int*)d_in[2];
    const int*   ix_out1 = (const int*)d_in[3];
    const int*   ix_in2  = (const int*)d_in[4];
    const int*   ix_in3  = (const int*)d_in[5];
    const int*   ix_out3 = (const int*)d_in[6];
    float* out = (float*)d_out;

    const int B = 256;
    layer0_kernel<<<(M0 / 2 + B - 1) / B, B>>>(x_pos, (const int4*)ix_in0, out);
    launch_pdl(segsum1_kernel, (E1 / 4 + B - 1) / B, B,
               (const int4*)ix_in1, (const int4*)ix_out1, ix_out1);
    launch_pdl(layer2_kernel, (M2 / 2 + B - 1) / B, B, (const int4*)ix_in2);
    launch_pdl(segsum3_kernel, (E3 / 4 + B - 1) / B, B,
               (const int4*)ix_in3, (const int4*)ix_out3, ix_out3, out);
}

// round 15
// speedup vs baseline: 1.0741x; 1.0741x over previous
#include <cuda_runtime.h>

#define NB_VARS 2000000
#define M0 4000000
#define M1 1000000
#define M2 500000
#define M3 125000
#define E1 8000000
#define E3 1000000

// Scratch (allocation-free rule: __device__ globals)
__device__ float g_y0[M0];
__device__ float g_y1[M1];
__device__ float g_y2[M2];

// Fused input encoding: x = [0, 1, p0, 1-p0, p1, 1-p1, ...]
__device__ __forceinline__ float leaf_val(const float* __restrict__ xp, int idx) {
    if (idx >= 2) {
        float p = __ldg(xp + ((idx - 2) >> 1));
        return (idx & 1) ? (1.0f - p) : p;
    }
    return (float)idx;  // 0 -> 0.0, 1 -> 1.0
}

// Layer 0: 2 products per thread (4 gathers), float2 store. 2M threads.
// Also zeroes g_y1 and d_out (PDL chain guarantees completion before consumers).
// Early trigger: lets segsum1's grid launch immediately and pre-issue its index streams.
__global__ void __launch_bounds__(256) layer0_kernel(const float* __restrict__ xp,
                                                     const int4* __restrict__ ix,
                                                     float* __restrict__ out_zero) {
    cudaTriggerProgrammaticLaunchCompletion();
    int t = blockIdx.x * blockDim.x + threadIdx.x;     // [0, M0/2)
    if (t < M1 / 4) ((float4*)g_y1)[t] = make_float4(0.f, 0.f, 0.f, 0.f);
    if (t < M3 / 4) ((float4*)out_zero)[t] = make_float4(0.f, 0.f, 0.f, 0.f);
    if (t >= M0 / 2) return;
    int4 v = __ldg(ix + t);
    float2 r;
    r.x = leaf_val(xp, v.x) * leaf_val(xp, v.y);
    r.y = leaf_val(xp, v.z) * leaf_val(xp, v.w);
    ((float2*)g_y0)[t] = r;
}

// Segsum layer 1: 4 edges/thread (2M threads), scan-free local run-merge + REDG.
// PDL: independent index streams issued and successor triggered BEFORE the grid
// dependency sync — overlaps layer0's mainloop/drain and hides launch latency.
__global__ void __launch_bounds__(256) segsum1_kernel(const int4* __restrict__ ix_in,
                                                      const int4* __restrict__ ix_out) {
    int t = blockIdx.x * blockDim.x + threadIdx.x;     // [0, E1/4)
    if (t >= E1 / 4) {
        cudaTriggerProgrammaticLaunchCompletion();
        cudaGridDependencySynchronize();
        return;
    }
    int4 s = __ldg(ix_out + t);
    int4 g = __ldg(ix_in + t);
    cudaTriggerProgrammaticLaunchCompletion();
    cudaGridDependencySynchronize();        // wait for layer0 (g_y0, zeroed g_y1)
    // 4 independent gathers in flight
    float v0 = __ldg(g_y0 + g.x);
    float v1 = __ldg(g_y0 + g.y);
    float v2 = __ldg(g_y0 + g.z);
    float v3 = __ldg(g_y0 + g.w);
    float acc = v0;
    int cur = s.x;
    if (s.y == cur) acc += v1; else { atomicAdd(g_y1 + cur, acc); cur = s.y; acc = v1; }
    if (s.z == cur) acc += v2; else { atomicAdd(g_y1 + cur, acc); cur = s.z; acc = v2; }
    if (s.w == cur) acc += v3; else { atomicAdd(g_y1 + cur, acc); cur = s.w; acc = v3; }
    atomicAdd(g_y1 + cur, acc);
}

// Layer 2: 2 products per thread over g_y1 -> g_y2. 250K threads. PDL as above.
__global__ void __launch_bounds__(256) layer2_kernel(const int4* __restrict__ ix) {
    int t = blockIdx.x * blockDim.x + threadIdx.x;     // [0, M2/2)
    if (t >= M2 / 2) {
        cudaTriggerProgrammaticLaunchCompletion();
        cudaGridDependencySynchronize();
        return;
    }
    int4 v = __ldg(ix + t);
    cudaTriggerProgrammaticLaunchCompletion();
    cudaGridDependencySynchronize();        // wait for segsum1 (g_y1 final)
    float2 r;
    r.x = __ldg(g_y1 + v.x) * __ldg(g_y1 + v.y);
    r.y = __ldg(g_y1 + v.z) * __ldg(g_y1 + v.w);
    ((float2*)g_y2)[t] = r;
}

// Segsum layer 3: 2 edges/thread (500K threads), pair merge + REDG. PDL as above.
__global__ void __launch_bounds__(256) segsum3_kernel(const int2* __restrict__ ix_in,
                                                      const int2* __restrict__ ix_out,
                                                      float* __restrict__ out) {
    int t = blockIdx.x * blockDim.x + threadIdx.x;     // [0, E3/2)
    if (t >= E3 / 2) {
        cudaGridDependencySynchronize();
        return;
    }
    int2 s = __ldg(ix_out + t);
    int2 g = __ldg(ix_in + t);
    cudaGridDependencySynchronize();        // wait for layer2 (g_y2; out zeroed transitively)
    float v0 = __ldg(g_y2 + g.x);
    float v1 = __ldg(g_y2 + g.y);
    if (s.x == s.y) {
        atomicAdd(out + s.x, v0 + v1);
    } else {
        atomicAdd(out + s.x, v0);
        atomicAdd(out + s.y, v1);
    }
}

template <typename... Args>
static void launch_pdl(void (*kern)(Args...), int grid, int block, Args... args) {
    cudaLaunchConfig_t cfg = {};
    cfg.gridDim = dim3(grid, 1, 1);
    cfg.blockDim = dim3(block, 1, 1);
    cudaLaunchAttribute attr[1];
    attr[0].id = cudaLaunchAttributeProgrammaticStreamSerialization;
    attr[0].val.programmaticStreamSerializationAllowed = 1;
    cfg.attrs = attr;
    cfg.numAttrs = 1;
    cfg.stream = 0;
    cudaLaunchKernelEx(&cfg, kern, args...);
}

extern "C" void kernel_launch(void* const* d_in, const int* in_sizes, int n_in,
                              void* d_out, int out_size) {
    const float* x_pos   = (const float*)d_in[0];
    const int*   ix_in0  = (const int*)d_in[1];
    const int*   ix_in1  = (const int*)d_in[2];
    const int*   ix_out1 = (const int*)d_in[3];
    const int*   ix_in2  = (const int*)d_in[4];
    const int*   ix_in3  = (const int*)d_in[5];
    const int*   ix_out3 = (const int*)d_in[6];
    float* out = (float*)d_out;

    const int B = 256;
    layer0_kernel<<<(M0 / 2 + B - 1) / B, B>>>(x_pos, (const int4*)ix_in0, out);
    launch_pdl(segsum1_kernel, (E1 / 4 + B - 1) / B, B,
               (const int4*)ix_in1, (const int4*)ix_out1);
    launch_pdl(layer2_kernel, (M2 / 2 + B - 1) / B, B, (const int4*)ix_in2);
    launch_pdl(segsum3_kernel, (E3 / 2 + B - 1) / B, B,
               (const int2*)ix_in3, (const int2*)ix_out3, out);
}